// round 16
// baseline (speedup 1.0000x reference)
#include <cuda_runtime.h>
#include <cstdint>

// Problem constants (fixed: N=4, M=8192, D=64, k=16)
#define NB 4
#define MP 8192
#define DD 64
#define KNN 16
#define TM 128
#define TN 128
#define NTILES (MP / TN)         // 64
#define NTHREADS 512
#define NEDGES (NB * MP * KNN)   // 524288

// smem byte offsets
#define SO_A   0                          // 3 splits x 128x64 bf16 = 49152
#define SO_B   49152                      // 2 bufs x 3 x 16384 = 98304
#define SO_D   147456                     // 128 x 134 f32 = 68608
#define PD     134
#define SO_X2R (SO_D + TM * PD * 4)       // 216064
#define SO_X2C (SO_X2R + 512)             // 216576 (2 bufs x 128 f32)
#define SMEM_BYTES (SO_X2C + 1024)        // 217600

__device__ unsigned short g_hi [NB * MP * DD];
__device__ unsigned short g_mid[NB * MP * DD];
__device__ unsigned short g_lo [NB * MP * DD];
__device__ float g_x2[NB * MP];

// round-to-nearest-even f32 -> bf16 bits (finite inputs)
__device__ __forceinline__ unsigned short rnbf(float v) {
    unsigned u = __float_as_uint(v);
    return (unsigned short)((u + 0x7fffu + ((u >> 16) & 1u)) >> 16);
}

// ---- prep: bf16 3-way split + squared norms ----
__global__ __launch_bounds__(256)
void prep_kernel(const float* __restrict__ x) {
    int t = blockIdx.x * 256 + threadIdx.x;      // 0..131071
    int p = t >> 2, c = t & 3;
    const float* src = x + (size_t)p * DD + c * 16;
    unsigned wh[8], wm[8], wl[8];
    #pragma unroll
    for (int j = 0; j < 8; ++j) {
        float v0 = src[2 * j], v1 = src[2 * j + 1];
        unsigned short h0 = rnbf(v0);
        float r0 = v0 - __uint_as_float((unsigned)h0 << 16);
        unsigned short m0 = rnbf(r0);
        unsigned short l0 = rnbf(r0 - __uint_as_float((unsigned)m0 << 16));
        unsigned short h1 = rnbf(v1);
        float r1 = v1 - __uint_as_float((unsigned)h1 << 16);
        unsigned short m1 = rnbf(r1);
        unsigned short l1 = rnbf(r1 - __uint_as_float((unsigned)m1 << 16));
        wh[j] = (unsigned)h0 | ((unsigned)h1 << 16);
        wm[j] = (unsigned)m0 | ((unsigned)m1 << 16);
        wl[j] = (unsigned)l0 | ((unsigned)l1 << 16);
    }
    size_t base = (size_t)p * DD + c * 16;
    *(uint4*)(g_hi  + base)     = make_uint4(wh[0], wh[1], wh[2], wh[3]);
    *(uint4*)(g_hi  + base + 8) = make_uint4(wh[4], wh[5], wh[6], wh[7]);
    *(uint4*)(g_mid + base)     = make_uint4(wm[0], wm[1], wm[2], wm[3]);
    *(uint4*)(g_mid + base + 8) = make_uint4(wm[4], wm[5], wm[6], wm[7]);
    *(uint4*)(g_lo  + base)     = make_uint4(wl[0], wl[1], wl[2], wl[3]);
    *(uint4*)(g_lo  + base + 8) = make_uint4(wl[4], wl[5], wl[6], wl[7]);

    if (t < NB * MP) {
        const float4* q = reinterpret_cast<const float4*>(x + (size_t)t * DD);
        float s = 0.f;
        #pragma unroll
        for (int i = 0; i < 16; ++i) {
            float4 v = q[i];
            s = fmaf(v.x, v.x, s); s = fmaf(v.y, v.y, s);
            s = fmaf(v.z, v.z, s); s = fmaf(v.w, v.w, s);
        }
        g_x2[t] = s;
    }
}

__device__ __forceinline__ void cp16(uint32_t dst, const void* src) {
    asm volatile("cp.async.cg.shared.global [%0], [%1], 16;" :: "r"(dst), "l"(src));
}
__device__ __forceinline__ void ldsm_x4(uint32_t* r, uint32_t a) {
    asm volatile("ldmatrix.sync.aligned.m8n8.x4.shared.b16 {%0,%1,%2,%3}, [%4];"
        : "=r"(r[0]), "=r"(r[1]), "=r"(r[2]), "=r"(r[3]) : "r"(a));
}
__device__ __forceinline__ void ldsm_x2(uint32_t* r, uint32_t a) {
    asm volatile("ldmatrix.sync.aligned.m8n8.x2.shared.b16 {%0,%1}, [%2];"
        : "=r"(r[0]), "=r"(r[1]) : "r"(a));
}
__device__ __forceinline__ void mma16816(float* d, const uint32_t* a, const uint32_t* b) {
    asm volatile("mma.sync.aligned.m16n8k16.row.col.f32.bf16.bf16.f32 "
        "{%0,%1,%2,%3}, {%4,%5,%6,%7}, {%8,%9}, {%0,%1,%2,%3};"
        : "+f"(d[0]), "+f"(d[1]), "+f"(d[2]), "+f"(d[3])
        : "r"(a[0]), "r"(a[1]), "r"(a[2]), "r"(a[3]), "r"(b[0]), "r"(b[1]));
}

__global__ __launch_bounds__(NTHREADS, 1)
void knn_mma_kernel(float* __restrict__ out, int write_dst) {
    extern __shared__ char smc[];
    const uint32_t su = (uint32_t)__cvta_generic_to_shared(smc);
    float* Dt  = (float*)(smc + SO_D);
    float* x2r = (float*)(smc + SO_X2R);
    float* xcs = (float*)(smc + SO_X2C);

    const int tid = threadIdx.x, warp = tid >> 5, lane = tid & 31;
    const int batch = blockIdx.x >> 6, rtile = blockIdx.x & 63;
    const int row0 = rtile * TM, pbase = batch * MP;
    const unsigned short* gs[3] = {g_hi, g_mid, g_lo};

    // ---- prologue: cp.async A (3 splits), B tile 0, norms ----
    #pragma unroll
    for (int it = 0; it < 6; ++it) {
        int idx = it * NTHREADS + tid, s = idx >> 10, rem = idx & 1023;
        int r = rem >> 3, ch = rem & 7;
        cp16(su + SO_A + s * 16384 + r * 128 + ((ch ^ (r & 7)) << 4),
             gs[s] + ((size_t)(pbase + row0 + r) * DD + ch * 8));
    }
    #pragma unroll
    for (int it = 0; it < 6; ++it) {
        int idx = it * NTHREADS + tid, s = idx >> 10, rem = idx & 1023;
        int n = rem >> 3, ch = rem & 7;
        cp16(su + SO_B + s * 16384 + n * 128 + ((ch ^ (n & 7)) << 4),
             gs[s] + ((size_t)(pbase + n) * DD + ch * 8));
    }
    if (tid < 32) {
        cp16(su + SO_X2R + tid * 16, g_x2 + pbase + row0 + tid * 4);
        cp16(su + SO_X2C + tid * 16, g_x2 + pbase + tid * 4);
    }
    asm volatile("cp.async.commit_group;");
    asm volatile("cp.async.wait_group 0;");
    __syncthreads();

    // 16 warps: 4x4 grid of 32x32 warp tiles
    const int WR = (warp >> 2) * 32, WC = (warp & 3) * 32;
    // ldmatrix lane addressing
    const int a_row = (lane & 7) + ((lane >> 3) & 1) * 8;  // within m16 tile
    const int a_cs  = lane >> 4;                           // k-chunk select 0/1
    const int l2    = lane & 15;
    const int b_nr  = l2 & 7;                              // within n8 tile
    const int b_cs  = l2 >> 3;

    // scan: 4 threads per row, 32 cols each
    const int srow = tid >> 2, sh = tid & 3;
    const float* drow = Dt + srow * PD + sh * 32;

    float best[KNN]; int bidx[KNN];
    #pragma unroll
    for (int i = 0; i < KNN; ++i) { best[i] = __int_as_float(0x7f800000); bidx[i] = 0; }
    float tau = __int_as_float(0x7f800000);

    for (int ct = 0; ct < NTILES; ++ct) {
        const int b = ct & 1;
        // prefetch next B + its norms (cp.async, overlaps everything below)
        if (ct + 1 < NTILES) {
            const int col0n = (ct + 1) * TN;
            #pragma unroll
            for (int it = 0; it < 6; ++it) {
                int idx = it * NTHREADS + tid, s = idx >> 10, rem = idx & 1023;
                int n = rem >> 3, ch = rem & 7;
                cp16(su + SO_B + (1 - b) * 49152 + s * 16384 + n * 128 + ((ch ^ (n & 7)) << 4),
                     gs[s] + ((size_t)(pbase + col0n + n) * DD + ch * 8));
            }
            if (tid < 32)
                cp16(su + SO_X2C + (1 - b) * 512 + tid * 16, g_x2 + pbase + col0n + tid * 4);
            asm volatile("cp.async.commit_group;");
        }

        // ---- MMA: 128x128x64, bf16x6 (hh,hm,mh,mm,hl,lh), warp tile 32x32 ----
        float acc[2][4][4];
        #pragma unroll
        for (int mi = 0; mi < 2; ++mi)
            #pragma unroll
            for (int ni = 0; ni < 4; ++ni)
                #pragma unroll
                for (int q = 0; q < 4; ++q) acc[mi][ni][q] = 0.f;

        const uint32_t abase = su + SO_A;
        const uint32_t bbase = su + SO_B + b * 49152;
        #pragma unroll
        for (int kc = 0; kc < 4; ++kc) {
            uint32_t af[3][2][4], bf[3][4][2];
            #pragma unroll
            for (int s = 0; s < 3; ++s) {
                #pragma unroll
                for (int mi = 0; mi < 2; ++mi) {
                    int row = WR + mi * 16 + a_row;
                    ldsm_x4(af[s][mi], abase + s * 16384 + row * 128
                                     + (((2 * kc + a_cs) ^ (row & 7)) << 4));
                }
                #pragma unroll
                for (int ni = 0; ni < 4; ++ni) {
                    int n = WC + ni * 8 + b_nr;
                    ldsm_x2(bf[s][ni], bbase + s * 16384 + n * 128
                                     + (((2 * kc + b_cs) ^ (n & 7)) << 4));
                }
            }
            const int SA[6] = {0, 0, 1, 1, 0, 2};
            const int SB[6] = {0, 1, 0, 1, 2, 0};
            #pragma unroll
            for (int t = 0; t < 6; ++t)
                #pragma unroll
                for (int mi = 0; mi < 2; ++mi)
                    #pragma unroll
                    for (int ni = 0; ni < 4; ++ni)
                        mma16816(acc[mi][ni], af[SA[t]][mi], bf[SB[t]][ni]);
        }

        // ---- scan previous tile's Dt ----
        if (ct > 0) {
            const int cbase = (ct - 1) * TN + sh * 32;
            #pragma unroll 4
            for (int c = 0; c < 32; ++c) {
                float v = drow[c];
                if (v < tau) {                       // strict <: stable ties
                    best[KNN - 1] = v;
                    bidx[KNN - 1] = cbase + c;
                    #pragma unroll
                    for (int u = KNN - 1; u > 0; --u) {
                        if (best[u] < best[u - 1]) {
                            float tv = best[u]; best[u] = best[u - 1]; best[u - 1] = tv;
                            int   ti = bidx[u]; bidx[u] = bidx[u - 1]; bidx[u - 1] = ti;
                        }
                    }
                    tau = best[KNN - 1];
                }
            }
        }
        __syncthreads();    // scans done -> Dt free for overwrite

        // ---- epilogue: d2 -> Dt ----
        {
            const float* xc = xcs + b * 128;
            #pragma unroll
            for (int mi = 0; mi < 2; ++mi) {
                int rl = WR + mi * 16 + (lane >> 2);
                float xrl = x2r[rl], xrh = x2r[rl + 8];
                #pragma unroll
                for (int ni = 0; ni < 4; ++ni) {
                    int col = WC + ni * 8 + (lane & 3) * 2;
                    float xc0 = xc[col], xc1 = xc[col + 1];
                    float2 lo, hi;
                    lo.x = fmaf(-2.f, acc[mi][ni][0], xrl + xc0);
                    lo.y = fmaf(-2.f, acc[mi][ni][1], xrl + xc1);
                    hi.x = fmaf(-2.f, acc[mi][ni][2], xrh + xc0);
                    hi.y = fmaf(-2.f, acc[mi][ni][3], xrh + xc1);
                    *(float2*)(Dt + rl * PD + col)       = lo;
                    *(float2*)(Dt + (rl + 8) * PD + col) = hi;
                }
            }
        }
        if (ct + 1 < NTILES) asm volatile("cp.async.wait_group 0;");
        __syncthreads();    // Dt(ct) visible; B(ct+1) landed
    }

    // ---- final scan (last tile) ----
    {
        const int cbase = (NTILES - 1) * TN + sh * 32;
        #pragma unroll 4
        for (int c = 0; c < 32; ++c) {
            float v = drow[c];
            if (v < tau) {
                best[KNN - 1] = v;
                bidx[KNN - 1] = cbase + c;
                #pragma unroll
                for (int u = KNN - 1; u > 0; --u) {
                    if (best[u] < best[u - 1]) {
                        float tv = best[u]; best[u] = best[u - 1]; best[u - 1] = tv;
                        int   ti = bidx[u]; bidx[u] = bidx[u - 1]; bidx[u - 1] = ti;
                    }
                }
                tau = best[KNN - 1];
            }
        }
    }
    __syncthreads();   // A/B regions no longer needed -> merge scratch

    float* mv  = (float*)(smc + SO_A);              // 512 lists x 16, stride 17
    int*   mi_ = (int*)(smc + SO_A + 512 * 17 * 4); // 34816B offset
    #pragma unroll
    for (int j = 0; j < KNN; ++j) {
        mv [tid * 17 + j] = best[j];
        mi_[tid * 17 + j] = bidx[j];
    }
    __syncthreads();

    // ---- 4-way merge per row (stable: min by (val, idx)) ----
    if (tid < TM) {
        const float* v[4]; const int* ix[4]; int p[4];
        #pragma unroll
        for (int j = 0; j < 4; ++j) {
            v[j]  = &mv [(4 * tid + j) * 17];
            ix[j] = &mi_[(4 * tid + j) * 17];
            p[j]  = 0;
        }
        const int gid  = pbase + row0 + tid;
        const int base = gid * KNN;
        #pragma unroll
        for (int t = 0; t < KNN; ++t) {
            float bv = __int_as_float(0x7f800000);
            int   bi = 0x7fffffff, sel = 0;
            #pragma unroll
            for (int j = 0; j < 4; ++j) {
                float a = (p[j] < KNN) ? v[j][p[j]] : __int_as_float(0x7f800000);
                int  ia = (p[j] < KNN) ? ix[j][p[j]] : 0x7fffffff;
                if (a < bv || (a == bv && ia < bi)) { bv = a; bi = ia; sel = j; }
            }
            ++p[sel];
            out[base + t] = (float)(bi + pbase);
        }
        if (write_dst) {
            float fg = (float)gid;
            #pragma unroll
            for (int t = 0; t < KNN; ++t) out[NEDGES + base + t] = fg;
        }
    }
}

extern "C" void kernel_launch(void* const* d_in, const int* in_sizes, int n_in,
                              void* d_out, int out_size) {
    // Bind x = largest input (robust to ordering and element/byte units).
    const float* x = (const float*)d_in[0];
    long long best_sz = -1;
    for (int i = 0; i < n_in; ++i) {
        if ((long long)in_sizes[i] > best_sz) {
            best_sz = in_sizes[i];
            x = (const float*)d_in[i];
        }
    }
    const int write_dst = (out_size >= 2 * NEDGES);

    prep_kernel<<<(NB * MP * 4) / 256, 256>>>(x);

    cudaFuncSetAttribute(knn_mma_kernel,
                         cudaFuncAttributeMaxDynamicSharedMemorySize, SMEM_BYTES);
    knn_mma_kernel<<<NB * (MP / TM), NTHREADS, SMEM_BYTES>>>((float*)d_out, write_dst);
}